// round 5
// baseline (speedup 1.0000x reference)
#include <cuda_runtime.h>
#include <cuda_bf16.h>
#include <math.h>
#include <stdint.h>

// ---------------------------------------------------------------------------
// GAT (4 heads x 32) + autoencoder head. R5: GEMMs on tensor cores via
// arch-portable mma.sync m16n8k16 bf16 (tcgen05 unavailable: harness PTX
// targets plain sm_103). fp32 accuracy via 3-term bf16 split as one K=384
// GEMM: A'=[hi|lo|hi], B'=[hi|hi|lo].
//   k_prep : W_cd = W_enc@W_dec, combined bias (tiny)
//   k1_gat : h = x@W_gat (MMA); logits + self-loop init of denom/agg
//   k_edge : one pass, red.v4 scatter
//   k_tail : x1=elu(agg/den+bg); MMA1 @Wcd; x2=elu(+bcd) in regs ->
//            A-frags for MMA2 @Wo; out = D2 + bo
// ---------------------------------------------------------------------------

#define MAXN 50176
#define TM 128
#define KS 392                    // padded K extent (elements) per operand row
#define SM_B_OFF (128 * KS * 2)   // A at 0, B at 100352
#define SMEM_TOT (2 * 128 * KS * 2)

__device__ __align__(16) float g_h[MAXN * 128];
__device__ __align__(16) float g_agg[MAXN * 128];
__device__ __align__(16) float g_asrc[MAXN * 4];
__device__ __align__(16) float g_adst[MAXN * 4];
__device__ __align__(16) float g_denom[MAXN * 4];
__device__ __align__(16) float g_Wcd[128 * 128];
__device__ __align__(16) float g_bcd[128];

__device__ __forceinline__ float lrelu(float v) { return v > 0.f ? v : 0.2f * v; }
__device__ __forceinline__ float elu(float v)   { return v > 0.f ? v : (expf(v) - 1.f); }

__device__ __forceinline__ void red4(float* addr, float a, float b, float c, float d) {
    asm volatile("red.global.add.v4.f32 [%0], {%1,%2,%3,%4};"
                 :: "l"(addr), "f"(a), "f"(b), "f"(c), "f"(d) : "memory");
}

__device__ __forceinline__ uint32_t smem_u32(const void* p) {
    uint32_t a;
    asm("{ .reg .u64 t; cvta.to.shared.u64 t, %1; cvt.u32.u64 %0, t; }" : "=r"(a) : "l"(p));
    return a;
}

#define LDSM_X4(r0, r1, r2, r3, addr)                                         \
    asm volatile("ldmatrix.sync.aligned.m8n8.x4.shared.b16 {%0,%1,%2,%3}, [%4];" \
                 : "=r"(r0), "=r"(r1), "=r"(r2), "=r"(r3) : "r"(addr))
#define LDSM_X2(r0, r1, addr)                                                 \
    asm volatile("ldmatrix.sync.aligned.m8n8.x2.shared.b16 {%0,%1}, [%2];"    \
                 : "=r"(r0), "=r"(r1) : "r"(addr))
#define MMA(c, a0, a1, a2, a3, b0, b1)                                        \
    asm volatile("mma.sync.aligned.m16n8k16.row.col.f32.bf16.bf16.f32 "       \
                 "{%0,%1,%2,%3}, {%4,%5,%6,%7}, {%8,%9}, {%0,%1,%2,%3};"      \
                 : "+f"((c)[0]), "+f"((c)[1]), "+f"((c)[2]), "+f"((c)[3])     \
                 : "r"(a0), "r"(a1), "r"(a2), "r"(a3), "r"(b0), "r"(b1))

__device__ __forceinline__ uint32_t pack2(__nv_bfloat16 lo, __nv_bfloat16 hi) {
    __nv_bfloat162 t; t.x = lo; t.y = hi;
    return *(uint32_t*)&t;
}

// Store fp32 pair (k even) into split operand row r: hi@k, lo@k+128, hi@k+256.
__device__ __forceinline__ void split_pair(char* base, int r, int k, float a, float b) {
    __nv_bfloat16 ha = __float2bfloat16(a), hb = __float2bfloat16(b);
    float la = a - __bfloat162float(ha), lb = b - __bfloat162float(hb);
    __nv_bfloat162 hp; hp.x = ha; hp.y = hb;
    __nv_bfloat162 lp; lp.x = __float2bfloat16(la); lp.y = __float2bfloat16(lb);
    *(__nv_bfloat162*)(base + (size_t)(r * KS + k) * 2)       = hp;
    *(__nv_bfloat162*)(base + (size_t)(r * KS + k + 128) * 2) = lp;
    *(__nv_bfloat162*)(base + (size_t)(r * KS + k + 256) * 2) = hp;
}
// B split: hi@k, hi@k+128, lo@k+256.
__device__ __forceinline__ void split_B(char* base, int r, int k, float v) {
    __nv_bfloat16 hb = __float2bfloat16(v);
    float lo = v - __bfloat162float(hb);
    *(__nv_bfloat16*)(base + (size_t)(r * KS + k) * 2)       = hb;
    *(__nv_bfloat16*)(base + (size_t)(r * KS + k + 128) * 2) = hb;
    *(__nv_bfloat16*)(base + (size_t)(r * KS + k + 256) * 2) = __float2bfloat16(lo);
}

// Shared GEMM core: warp wid computes rows wid*16..+15 x cols 0..127 into acc[16][4].
__device__ __forceinline__ void gemm_k384(uint32_t sbA, uint32_t sbB,
                                          int wid, int lane, float acc[16][4]) {
    uint32_t aaddr = sbA + (uint32_t)(((wid * 16 + (lane & 15)) * KS + (lane >> 4) * 8) * 2);
    int l2 = lane & 15;
    uint32_t baddr = sbB + (uint32_t)((((l2 & 7)) * KS + (l2 >> 3) * 8) * 2);
    #pragma unroll
    for (int kc = 0; kc < 24; kc++) {
        uint32_t a0, a1, a2, a3;
        LDSM_X4(a0, a1, a2, a3, aaddr + kc * 32);
        #pragma unroll
        for (int nt = 0; nt < 16; nt++) {
            uint32_t b0, b1;
            LDSM_X2(b0, b1, baddr + nt * (8 * KS * 2) + kc * 32);
            MMA(acc[nt], a0, a1, a2, a3, b0, b1);
        }
    }
}

// ---------------------------------------------------------------------------
__global__ void k_prep(const float* __restrict__ We, const float* __restrict__ Wd,
                       const float* __restrict__ be, const float* __restrict__ bd) {
    int r = blockIdx.x, j = threadIdx.x;
    if (r < 128) {
        float a = 0.f;
        #pragma unroll
        for (int k = 0; k < 64; k++) a += We[r * 64 + k] * Wd[k * 128 + j];
        g_Wcd[r * 128 + j] = a;
    } else {
        float a = bd[j];
        #pragma unroll
        for (int k = 0; k < 64; k++) a += be[k] * Wd[k * 128 + j];
        g_bcd[j] = a;
    }
}

// ---------------------------------------------------------------------------
// k1_gat: h = x @ W_gat (tensor); epilogue: logits + self-loop init.
// ---------------------------------------------------------------------------
__global__ __launch_bounds__(256) void k1_gat(
    const float* __restrict__ x, const float* __restrict__ Wg,
    const float* __restrict__ att_s, const float* __restrict__ att_d, int N) {
    extern __shared__ char smem[];
    uint32_t sb = smem_u32(smem);
    int tid = threadIdx.x, wid = tid >> 5, lane = tid & 31;
    int row0 = blockIdx.x * TM;

    // A = x rows (split bf16)
    const float4* x4 = (const float4*)x;
    for (int i = tid; i < TM * 32; i += 256) {
        int r = i >> 5, c4 = i & 31, gr = row0 + r;
        float4 v = (gr < N) ? x4[(size_t)gr * 32 + c4] : make_float4(0.f, 0.f, 0.f, 0.f);
        split_pair(smem, r, c4 * 4, v.x, v.y);
        split_pair(smem, r, c4 * 4 + 2, v.z, v.w);
    }
    // B = Wg^T rows [n][k]
    const float4* W4 = (const float4*)Wg;
    for (int i = tid; i < 4096; i += 256) {
        int k = i >> 5, n0 = (i & 31) * 4;
        float4 w = W4[i];
        split_B(smem + SM_B_OFF, n0 + 0, k, w.x);
        split_B(smem + SM_B_OFF, n0 + 1, k, w.y);
        split_B(smem + SM_B_OFF, n0 + 2, k, w.z);
        split_B(smem + SM_B_OFF, n0 + 3, k, w.w);
    }
    __syncthreads();

    float acc[16][4];
    #pragma unroll
    for (int i = 0; i < 16; i++)
        #pragma unroll
        for (int j = 0; j < 4; j++) acc[i][j] = 0.f;
    gemm_k384(sb, sb + SM_B_OFF, wid, lane, acc);

    // Epilogue: lane owns rows g=lane>>2 (A) and g+8 (B) of the warp's 16,
    // cols nt*8 + (lane&3)*2 {+1}.
    int g = lane >> 2, q = lane & 3;
    int grA = row0 + wid * 16 + g;
    int grB = grA + 8;
    float pa[4], pb[4];
    #pragma unroll
    for (int hh = 0; hh < 4; hh++) {
        float sAs = 0.f, sAd = 0.f, sBs = 0.f, sBd = 0.f;
        #pragma unroll
        for (int t = 0; t < 4; t++) {
            int nt = hh * 4 + t;
            int c0 = nt * 8 + q * 2;
            float w0s = __ldg(&att_s[c0]), w1s = __ldg(&att_s[c0 + 1]);
            float w0d = __ldg(&att_d[c0]), w1d = __ldg(&att_d[c0 + 1]);
            sAs += acc[nt][0] * w0s + acc[nt][1] * w1s;
            sAd += acc[nt][0] * w0d + acc[nt][1] * w1d;
            sBs += acc[nt][2] * w0s + acc[nt][3] * w1s;
            sBd += acc[nt][2] * w0d + acc[nt][3] * w1d;
        }
        #pragma unroll
        for (int off = 1; off <= 2; off <<= 1) {
            sAs += __shfl_xor_sync(0xffffffffu, sAs, off);
            sAd += __shfl_xor_sync(0xffffffffu, sAd, off);
            sBs += __shfl_xor_sync(0xffffffffu, sBs, off);
            sBd += __shfl_xor_sync(0xffffffffu, sBd, off);
        }
        pa[hh] = expf(lrelu(sAs + sAd));
        pb[hh] = expf(lrelu(sBs + sBd));
        if (q == 0) {
            if (grA < N) {
                g_asrc[grA * 4 + hh] = sAs; g_adst[grA * 4 + hh] = sAd;
                g_denom[grA * 4 + hh] = pa[hh];
            }
            if (grB < N) {
                g_asrc[grB * 4 + hh] = sBs; g_adst[grB * 4 + hh] = sBd;
                g_denom[grB * 4 + hh] = pb[hh];
            }
        }
    }
    #pragma unroll
    for (int nt = 0; nt < 16; nt++) {
        int c0 = nt * 8 + q * 2;
        float pA = pa[nt >> 2], pB = pb[nt >> 2];
        if (grA < N) {
            *(float2*)&g_h[(size_t)grA * 128 + c0] = make_float2(acc[nt][0], acc[nt][1]);
            *(float2*)&g_agg[(size_t)grA * 128 + c0] =
                make_float2(pA * acc[nt][0], pA * acc[nt][1]);
        }
        if (grB < N) {
            *(float2*)&g_h[(size_t)grB * 128 + c0] = make_float2(acc[nt][2], acc[nt][3]);
            *(float2*)&g_agg[(size_t)grB * 128 + c0] =
                make_float2(pB * acc[nt][2], pB * acc[nt][3]);
        }
    }
}

// ---------------------------------------------------------------------------
// One warp per edge: coalesced 512B read of h[src], vector reductions to dst.
// ---------------------------------------------------------------------------
__global__ __launch_bounds__(256) void k_edge(const int* __restrict__ ei, int E) {
    int e = blockIdx.x * 8 + (threadIdx.x >> 5);
    if (e >= E) return;
    int lane = threadIdx.x & 31;
    int s = ei[e];
    int d = ei[E + e];

    float4 as = ((const float4*)g_asrc)[s];
    float4 ad = ((const float4*)g_adst)[d];
    float asv = lane < 16 ? (lane < 8 ? as.x : as.y) : (lane < 24 ? as.z : as.w);
    float adv = lane < 16 ? (lane < 8 ? ad.x : ad.y) : (lane < 24 ? ad.z : ad.w);
    float ev = asv + adv;
    float p = expf(ev > 0.f ? ev : 0.2f * ev);

    float p1 = __shfl_sync(0xffffffffu, p, 8);
    float p2 = __shfl_sync(0xffffffffu, p, 16);
    float p3 = __shfl_sync(0xffffffffu, p, 24);
    if (lane == 0) red4(&g_denom[(size_t)d * 4], p, p1, p2, p3);

    float4 hv = ((const float4*)g_h)[(size_t)s * 32 + lane];
    red4(&g_agg[(size_t)d * 128 + lane * 4], p * hv.x, p * hv.y, p * hv.z, p * hv.w);
}

// ---------------------------------------------------------------------------
// k_tail: x1=elu(agg/den+bg); MMA1 @Wcd; x2=elu(D1+bcd) packed in-register
// into MMA2 A-frags (D-frag layout == A-frag layout); B rebuilt = Wo^T;
// MMA2; out = D2 + bo.
// ---------------------------------------------------------------------------
__global__ __launch_bounds__(256) void k_tail(
    const float* __restrict__ bg, const float* __restrict__ Wo,
    const float* __restrict__ bo, float* __restrict__ out, int N) {
    extern __shared__ char smem[];
    uint32_t sb = smem_u32(smem);
    int tid = threadIdx.x, wid = tid >> 5, lane = tid & 31;
    int row0 = blockIdx.x * TM;

    // A = x1 rows
    const float4* agg4 = (const float4*)g_agg;
    const float4* bg4 = (const float4*)bg;
    for (int i = tid; i < TM * 32; i += 256) {
        int r = i >> 5, c4 = i & 31, gr = row0 + r;
        float4 v = make_float4(0.f, 0.f, 0.f, 0.f);
        if (gr < N) {
            float4 a = agg4[(size_t)gr * 32 + c4];
            float inv = 1.f / (g_denom[gr * 4 + (c4 >> 3)] + 1e-16f);
            float4 b = bg4[c4];
            v.x = elu(a.x * inv + b.x); v.y = elu(a.y * inv + b.y);
            v.z = elu(a.z * inv + b.z); v.w = elu(a.w * inv + b.w);
        }
        split_pair(smem, r, c4 * 4, v.x, v.y);
        split_pair(smem, r, c4 * 4 + 2, v.z, v.w);
    }
    // B1 = Wcd^T
    const float4* Wc4 = (const float4*)g_Wcd;
    for (int i = tid; i < 4096; i += 256) {
        int k = i >> 5, n0 = (i & 31) * 4;
        float4 w = Wc4[i];
        split_B(smem + SM_B_OFF, n0 + 0, k, w.x);
        split_B(smem + SM_B_OFF, n0 + 1, k, w.y);
        split_B(smem + SM_B_OFF, n0 + 2, k, w.z);
        split_B(smem + SM_B_OFF, n0 + 3, k, w.w);
    }
    __syncthreads();

    float acc[16][4];
    #pragma unroll
    for (int i = 0; i < 16; i++)
        #pragma unroll
        for (int j = 0; j < 4; j++) acc[i][j] = 0.f;
    gemm_k384(sb, sb + SM_B_OFF, wid, lane, acc);
    __syncthreads();   // GEMM1 reads of B done

    // x2 = elu(D1 + bcd); pack A-frags (hi & lo) in registers.
    int q = lane & 3;
    uint32_t ah[8][4], al[8][4];
    #pragma unroll
    for (int j = 0; j < 8; j++) {
        #pragma unroll
        for (int hf = 0; hf < 2; hf++) {
            int nt = 2 * j + hf;
            int c0 = nt * 8 + q * 2;
            float bc0 = g_bcd[c0], bc1 = g_bcd[c0 + 1];
            float v0 = elu(acc[nt][0] + bc0), v1 = elu(acc[nt][1] + bc1);
            float v2 = elu(acc[nt][2] + bc0), v3 = elu(acc[nt][3] + bc1);
            __nv_bfloat16 h0 = __float2bfloat16(v0), h1 = __float2bfloat16(v1);
            __nv_bfloat16 h2 = __float2bfloat16(v2), h3 = __float2bfloat16(v3);
            ah[j][hf * 2 + 0] = pack2(h0, h1);
            ah[j][hf * 2 + 1] = pack2(h2, h3);
            al[j][hf * 2 + 0] = pack2(__float2bfloat16(v0 - __bfloat162float(h0)),
                                      __float2bfloat16(v1 - __bfloat162float(h1)));
            al[j][hf * 2 + 1] = pack2(__float2bfloat16(v2 - __bfloat162float(h2)),
                                      __float2bfloat16(v3 - __bfloat162float(h3)));
        }
    }

    // B2 = Wo^T
    const float4* Wo4 = (const float4*)Wo;
    for (int i = tid; i < 4096; i += 256) {
        int k = i >> 5, n0 = (i & 31) * 4;
        float4 w = Wo4[i];
        split_B(smem + SM_B_OFF, n0 + 0, k, w.x);
        split_B(smem + SM_B_OFF, n0 + 1, k, w.y);
        split_B(smem + SM_B_OFF, n0 + 2, k, w.z);
        split_B(smem + SM_B_OFF, n0 + 3, k, w.w);
    }
    __syncthreads();

    float ac2[16][4];
    #pragma unroll
    for (int i = 0; i < 16; i++)
        #pragma unroll
        for (int j = 0; j < 4; j++) ac2[i][j] = 0.f;
    {
        int l2 = lane & 15;
        uint32_t baddr = sb + SM_B_OFF + (uint32_t)((((l2 & 7)) * KS + (l2 >> 3) * 8) * 2);
        #pragma unroll
        for (int kc = 0; kc < 24; kc++) {
            int j = kc & 7;
            uint32_t a0, a1, a2, a3;
            if (kc < 8)       { a0 = ah[j][0]; a1 = ah[j][1]; a2 = ah[j][2]; a3 = ah[j][3]; }
            else if (kc < 16) { a0 = al[j][0]; a1 = al[j][1]; a2 = al[j][2]; a3 = al[j][3]; }
            else              { a0 = ah[j][0]; a1 = ah[j][1]; a2 = ah[j][2]; a3 = ah[j][3]; }
            #pragma unroll
            for (int nt = 0; nt < 16; nt++) {
                uint32_t b0, b1;
                LDSM_X2(b0, b1, baddr + nt * (8 * KS * 2) + kc * 32);
                MMA(ac2[nt], a0, a1, a2, a3, b0, b1);
            }
        }
    }

    int g = lane >> 2;
    int grA = row0 + wid * 16 + g;
    int grB = grA + 8;
    #pragma unroll
    for (int nt = 0; nt < 16; nt++) {
        int c0 = nt * 8 + q * 2;
        float b0 = __ldg(&bo[c0]), b1 = __ldg(&bo[c0 + 1]);
        if (grA < N)
            *(float2*)&out[(size_t)grA * 128 + c0] =
                make_float2(ac2[nt][0] + b0, ac2[nt][1] + b1);
        if (grB < N)
            *(float2*)&out[(size_t)grB * 128 + c0] =
                make_float2(ac2[nt][2] + b0, ac2[nt][3] + b1);
    }
}

// ---------------------------------------------------------------------------

extern "C" void kernel_launch(void* const* d_in, const int* in_sizes, int n_in,
                              void* d_out, int out_size) {
    const float* x     = (const float*)d_in[0];
    const int*   ei    = (const int*)d_in[1];
    const float* Wg    = (const float*)d_in[2];
    const float* bg    = (const float*)d_in[3];
    const float* att_s = (const float*)d_in[4];
    const float* att_d = (const float*)d_in[5];
    const float* We    = (const float*)d_in[6];
    const float* be    = (const float*)d_in[7];
    const float* Wd    = (const float*)d_in[8];
    const float* bd    = (const float*)d_in[9];
    const float* Wo    = (const float*)d_in[10];
    const float* bo    = (const float*)d_in[11];
    float* out = (float*)d_out;

    int N = in_sizes[0] / 128;
    int E = in_sizes[1] / 2;

    cudaFuncSetAttribute(k1_gat, cudaFuncAttributeMaxDynamicSharedMemorySize, SMEM_TOT);
    cudaFuncSetAttribute(k_tail, cudaFuncAttributeMaxDynamicSharedMemorySize, SMEM_TOT);

    int nb = (N + TM - 1) / TM;

    k_prep<<<129, 128>>>(We, Wd, be, bd);
    k1_gat<<<nb, 256, SMEM_TOT>>>(x, Wg, att_s, att_d, N);
    k_edge<<<(E + 7) / 8, 256>>>(ei, E);
    k_tail<<<nb, 256, SMEM_TOT>>>(bg, Wo, bo, out, N);
}

// round 6
// speedup vs baseline: 1.4833x; 1.4833x over previous
#include <cuda_runtime.h>
#include <cuda_bf16.h>
#include <math.h>
#include <stdint.h>

// ---------------------------------------------------------------------------
// GAT (4x32 heads) + autoencoder head. R6: mma.sync bf16 with compact hi/lo
// split (K=256 storage, 3 passes: hi*hi + lo*hi + hi*lo), TM=64 (2 CTAs/SM),
// B fragments via ldmatrix.x4, B matrices pre-split once in k_prep2.
// ---------------------------------------------------------------------------

#define MAXN 50176
#define TM 64
#define KS2 264                       // padded row extent (elements)
#define SM_B (TM * KS2 * 2)           // A: 33792 B, then B: 128*KS2*2 = 67584
#define SMEM_TOT (SM_B + 128 * KS2 * 2)

__device__ __align__(16) float g_h[MAXN * 128];
__device__ __align__(16) float g_agg[MAXN * 128];
__device__ __align__(16) float g_asrc[MAXN * 4];
__device__ __align__(16) float g_adst[MAXN * 4];
__device__ __align__(16) float g_denom[MAXN * 4];
__device__ __align__(16) float g_Wcd[128 * 128];
__device__ __align__(16) float g_bcd[128];
__device__ __align__(16) __nv_bfloat16 g_BgT[128 * KS2];
__device__ __align__(16) __nv_bfloat16 g_BcdT[128 * KS2];
__device__ __align__(16) __nv_bfloat16 g_BoT[128 * KS2];

__device__ __forceinline__ float lrelu(float v) { return v > 0.f ? v : 0.2f * v; }
__device__ __forceinline__ float elu(float v)   { return v > 0.f ? v : (expf(v) - 1.f); }

__device__ __forceinline__ void red4(float* addr, float a, float b, float c, float d) {
    asm volatile("red.global.add.v4.f32 [%0], {%1,%2,%3,%4};"
                 :: "l"(addr), "f"(a), "f"(b), "f"(c), "f"(d) : "memory");
}

__device__ __forceinline__ uint32_t smem_u32(const void* p) {
    uint32_t a;
    asm("{ .reg .u64 t; cvta.to.shared.u64 t, %1; cvt.u32.u64 %0, t; }" : "=r"(a) : "l"(p));
    return a;
}

#define LDSM_X4(r0, r1, r2, r3, addr)                                         \
    asm volatile("ldmatrix.sync.aligned.m8n8.x4.shared.b16 {%0,%1,%2,%3}, [%4];" \
                 : "=r"(r0), "=r"(r1), "=r"(r2), "=r"(r3) : "r"(addr))
#define MMA(c, a0, a1, a2, a3, b0, b1)                                        \
    asm volatile("mma.sync.aligned.m16n8k16.row.col.f32.bf16.bf16.f32 "       \
                 "{%0,%1,%2,%3}, {%4,%5,%6,%7}, {%8,%9}, {%0,%1,%2,%3};"      \
                 : "+f"((c)[0]), "+f"((c)[1]), "+f"((c)[2]), "+f"((c)[3])     \
                 : "r"(a0), "r"(a1), "r"(a2), "r"(a3), "r"(b0), "r"(b1))

// Store fp32 pair (even k) into A row r: hi at k, lo at k+128.
__device__ __forceinline__ void split2(char* base, int r, int k, float a, float b) {
    __nv_bfloat16 ha = __float2bfloat16(a), hb = __float2bfloat16(b);
    __nv_bfloat162 hp; hp.x = ha; hp.y = hb;
    __nv_bfloat162 lp;
    lp.x = __float2bfloat16(a - __bfloat162float(ha));
    lp.y = __float2bfloat16(b - __bfloat162float(hb));
    *(__nv_bfloat162*)(base + (size_t)(r * KS2 + k) * 2)       = hp;
    *(__nv_bfloat162*)(base + (size_t)(r * KS2 + k + 128) * 2) = lp;
}

// GEMM core: warp (wm, wn) computes rows wm*16..+15 x cols wn*64..+63 over
// K=128 fp32 (3 bf16 passes). acc[8][4] per lane.
__device__ __forceinline__ void gemm3(uint32_t sbA, uint32_t sbB,
                                      int wm, int wn, int lane, float acc[8][4]) {
    uint32_t arow = (uint32_t)(wm * 16 + (lane & 15));
    uint32_t aka  = (uint32_t)((lane >> 4) * 8);
    uint32_t brow = (uint32_t)(wn * 64 + ((lane >> 4) << 3) + (lane & 7));
    uint32_t bka  = (uint32_t)(((lane >> 3) & 1) * 8);
    #pragma unroll
    for (int p = 0; p < 3; p++) {
        int aOff = (p == 1) ? 128 : 0;
        int bOff = (p == 2) ? 128 : 0;
        uint32_t abase = sbA + (arow * KS2 + aOff + aka) * 2;
        uint32_t bbase = sbB + (brow * KS2 + bOff + bka) * 2;
        #pragma unroll
        for (int kc = 0; kc < 8; kc++) {
            uint32_t a0, a1, a2, a3;
            LDSM_X4(a0, a1, a2, a3, abase + kc * 32);
            #pragma unroll
            for (int np = 0; np < 4; np++) {
                uint32_t b0, b1, b2, b3;
                LDSM_X4(b0, b1, b2, b3, bbase + np * (16 * KS2 * 2) + kc * 32);
                MMA(acc[2 * np],     a0, a1, a2, a3, b0, b1);
                MMA(acc[2 * np + 1], a0, a1, a2, a3, b2, b3);
            }
        }
    }
}

__device__ __forceinline__ void copyB(char* smem, const __nv_bfloat16* src, int tid) {
    const float4* s4 = (const float4*)src;
    float4* d4 = (float4*)(smem + SM_B);
    #pragma unroll 4
    for (int i = tid; i < 128 * KS2 / 8; i += 256) d4[i] = s4[i];
}

// ---------------------------------------------------------------------------
__global__ void k_prep(const float* __restrict__ We, const float* __restrict__ Wd,
                       const float* __restrict__ be, const float* __restrict__ bd) {
    int r = blockIdx.x, j = threadIdx.x;
    if (r < 128) {
        float a = 0.f;
        #pragma unroll
        for (int k = 0; k < 64; k++) a += We[r * 64 + k] * Wd[k * 128 + j];
        g_Wcd[r * 128 + j] = a;
    } else {
        float a = bd[j];
        #pragma unroll
        for (int k = 0; k < 64; k++) a += be[k] * Wd[k * 128 + j];
        g_bcd[j] = a;
    }
}

// Pre-split B matrices (transposed, hi|lo layout) into global.
__global__ void k_prep2(const float* __restrict__ Wg, const float* __restrict__ Wo) {
    int n = blockIdx.x, k = threadIdx.x;
    float v;
    __nv_bfloat16 hb;
    v = Wg[k * 128 + n]; hb = __float2bfloat16(v);
    g_BgT[n * KS2 + k] = hb;
    g_BgT[n * KS2 + 128 + k] = __float2bfloat16(v - __bfloat162float(hb));
    v = g_Wcd[k * 128 + n]; hb = __float2bfloat16(v);
    g_BcdT[n * KS2 + k] = hb;
    g_BcdT[n * KS2 + 128 + k] = __float2bfloat16(v - __bfloat162float(hb));
    v = Wo[k * 128 + n]; hb = __float2bfloat16(v);
    g_BoT[n * KS2 + k] = hb;
    g_BoT[n * KS2 + 128 + k] = __float2bfloat16(v - __bfloat162float(hb));
}

// ---------------------------------------------------------------------------
// k1_gat: h = x @ W_gat (tensor); epilogue: logits + self-loop init.
// ---------------------------------------------------------------------------
__global__ __launch_bounds__(256, 2) void k1_gat(
    const float* __restrict__ x, const float* __restrict__ att_s,
    const float* __restrict__ att_d, int N) {
    extern __shared__ char smem[];
    uint32_t sb = smem_u32(smem);
    int tid = threadIdx.x, wid = tid >> 5, lane = tid & 31;
    int wm = wid >> 1, wn = wid & 1;
    int row0 = blockIdx.x * TM;

    // A = x rows (split)
    const float4* x4 = (const float4*)x;
    for (int i = tid; i < TM * 32; i += 256) {
        int r = i >> 5, c4 = i & 31, gr = row0 + r;
        float4 v = (gr < N) ? x4[(size_t)gr * 32 + c4] : make_float4(0.f, 0.f, 0.f, 0.f);
        split2(smem, r, c4 * 4, v.x, v.y);
        split2(smem, r, c4 * 4 + 2, v.z, v.w);
    }
    copyB(smem, g_BgT, tid);
    __syncthreads();

    float acc[8][4];
    #pragma unroll
    for (int i = 0; i < 8; i++)
        #pragma unroll
        for (int j = 0; j < 4; j++) acc[i][j] = 0.f;
    gemm3(sb, sb + SM_B, wm, wn, lane, acc);

    // Epilogue: lane owns rows g, g+8 of warp's 16; cols wn*64 + nt*8 + q*2.
    int g = lane >> 2, q = lane & 3;
    int grA = row0 + wm * 16 + g;
    int grB = grA + 8;
    float pa[2], pb[2];
    #pragma unroll
    for (int hl = 0; hl < 2; hl++) {                  // local head
        int hh = wn * 2 + hl;
        float sAs = 0.f, sAd = 0.f, sBs = 0.f, sBd = 0.f;
        #pragma unroll
        for (int t = 0; t < 4; t++) {
            int nt = hl * 4 + t;
            int c0 = wn * 64 + nt * 8 + q * 2;        // global col; att flat [h*32+c]
            float w0s = __ldg(&att_s[c0]), w1s = __ldg(&att_s[c0 + 1]);
            float w0d = __ldg(&att_d[c0]), w1d = __ldg(&att_d[c0 + 1]);
            sAs += acc[nt][0] * w0s + acc[nt][1] * w1s;
            sAd += acc[nt][0] * w0d + acc[nt][1] * w1d;
            sBs += acc[nt][2] * w0s + acc[nt][3] * w1s;
            sBd += acc[nt][2] * w0d + acc[nt][3] * w1d;
        }
        #pragma unroll
        for (int off = 1; off <= 2; off <<= 1) {
            sAs += __shfl_xor_sync(0xffffffffu, sAs, off);
            sAd += __shfl_xor_sync(0xffffffffu, sAd, off);
            sBs += __shfl_xor_sync(0xffffffffu, sBs, off);
            sBd += __shfl_xor_sync(0xffffffffu, sBd, off);
        }
        pa[hl] = expf(lrelu(sAs + sAd));
        pb[hl] = expf(lrelu(sBs + sBd));
        if (q == 0) {
            if (grA < N) {
                g_asrc[grA * 4 + hh] = sAs; g_adst[grA * 4 + hh] = sAd;
                g_denom[grA * 4 + hh] = pa[hl];
            }
            if (grB < N) {
                g_asrc[grB * 4 + hh] = sBs; g_adst[grB * 4 + hh] = sBd;
                g_denom[grB * 4 + hh] = pb[hl];
            }
        }
    }
    #pragma unroll
    for (int nt = 0; nt < 8; nt++) {
        int c0 = wn * 64 + nt * 8 + q * 2;
        float pA = pa[nt >> 2], pB = pb[nt >> 2];
        if (grA < N) {
            *(float2*)&g_h[(size_t)grA * 128 + c0] = make_float2(acc[nt][0], acc[nt][1]);
            *(float2*)&g_agg[(size_t)grA * 128 + c0] =
                make_float2(pA * acc[nt][0], pA * acc[nt][1]);
        }
        if (grB < N) {
            *(float2*)&g_h[(size_t)grB * 128 + c0] = make_float2(acc[nt][2], acc[nt][3]);
            *(float2*)&g_agg[(size_t)grB * 128 + c0] =
                make_float2(pB * acc[nt][2], pB * acc[nt][3]);
        }
    }
}

// ---------------------------------------------------------------------------
// One warp per edge: coalesced 512B read of h[src], vector reductions to dst.
// ---------------------------------------------------------------------------
__global__ __launch_bounds__(256) void k_edge(const int* __restrict__ ei, int E) {
    int e = blockIdx.x * 8 + (threadIdx.x >> 5);
    if (e >= E) return;
    int lane = threadIdx.x & 31;
    int s = ei[e];
    int d = ei[E + e];

    float4 as = ((const float4*)g_asrc)[s];
    float4 ad = ((const float4*)g_adst)[d];
    float asv = lane < 16 ? (lane < 8 ? as.x : as.y) : (lane < 24 ? as.z : as.w);
    float adv = lane < 16 ? (lane < 8 ? ad.x : ad.y) : (lane < 24 ? ad.z : ad.w);
    float ev = asv + adv;
    float p = expf(ev > 0.f ? ev : 0.2f * ev);

    float p1 = __shfl_sync(0xffffffffu, p, 8);
    float p2 = __shfl_sync(0xffffffffu, p, 16);
    float p3 = __shfl_sync(0xffffffffu, p, 24);
    if (lane == 0) red4(&g_denom[(size_t)d * 4], p, p1, p2, p3);

    float4 hv = ((const float4*)g_h)[(size_t)s * 32 + lane];
    red4(&g_agg[(size_t)d * 128 + lane * 4], p * hv.x, p * hv.y, p * hv.z, p * hv.w);
}

// ---------------------------------------------------------------------------
// k_tail: x1=elu(agg/den+bg); GEMM1 @Wcd; x2=elu(+bcd) -> A smem; B<-Wo^T;
// GEMM2; out = D2 + bo.
// ---------------------------------------------------------------------------
__global__ __launch_bounds__(256, 2) void k_tail(
    const float* __restrict__ bg, const float* __restrict__ bo,
    float* __restrict__ out, int N) {
    extern __shared__ char smem[];
    uint32_t sb = smem_u32(smem);
    int tid = threadIdx.x, wid = tid >> 5, lane = tid & 31;
    int wm = wid >> 1, wn = wid & 1;
    int row0 = blockIdx.x * TM;

    // A = x1 rows
    const float4* agg4 = (const float4*)g_agg;
    const float4* bg4 = (const float4*)bg;
    for (int i = tid; i < TM * 32; i += 256) {
        int r = i >> 5, c4 = i & 31, gr = row0 + r;
        float4 v = make_float4(0.f, 0.f, 0.f, 0.f);
        if (gr < N) {
            float4 a = agg4[(size_t)gr * 32 + c4];
            float inv = 1.f / (g_denom[gr * 4 + (c4 >> 3)] + 1e-16f);
            float4 b = bg4[c4];
            v.x = elu(a.x * inv + b.x); v.y = elu(a.y * inv + b.y);
            v.z = elu(a.z * inv + b.z); v.w = elu(a.w * inv + b.w);
        }
        split2(smem, r, c4 * 4, v.x, v.y);
        split2(smem, r, c4 * 4 + 2, v.z, v.w);
    }
    copyB(smem, g_BcdT, tid);
    __syncthreads();

    float acc[8][4];
    #pragma unroll
    for (int i = 0; i < 8; i++)
        #pragma unroll
        for (int j = 0; j < 4; j++) acc[i][j] = 0.f;
    gemm3(sb, sb + SM_B, wm, wn, lane, acc);
    __syncthreads();                    // all operand reads done

    // x2 = elu(D1 + bcd) -> A smem (split); rebuild B = Wo^T.
    int g = lane >> 2, q = lane & 3;
    int lrA = wm * 16 + g, lrB = lrA + 8;
    #pragma unroll
    for (int nt = 0; nt < 8; nt++) {
        int c0 = wn * 64 + nt * 8 + q * 2;
        float bc0 = g_bcd[c0], bc1 = g_bcd[c0 + 1];
        split2(smem, lrA, c0, elu(acc[nt][0] + bc0), elu(acc[nt][1] + bc1));
        split2(smem, lrB, c0, elu(acc[nt][2] + bc0), elu(acc[nt][3] + bc1));
    }
    copyB(smem, g_BoT, tid);
    __syncthreads();

    #pragma unroll
    for (int i = 0; i < 8; i++)
        #pragma unroll
        for (int j = 0; j < 4; j++) acc[i][j] = 0.f;
    gemm3(sb, sb + SM_B, wm, wn, lane, acc);

    int grA = row0 + lrA, grB = row0 + lrB;
    #pragma unroll
    for (int nt = 0; nt < 8; nt++) {
        int c0 = wn * 64 + nt * 8 + q * 2;
        float b0 = __ldg(&bo[c0]), b1 = __ldg(&bo[c0 + 1]);
        if (grA < N)
            *(float2*)&out[(size_t)grA * 128 + c0] =
                make_float2(acc[nt][0] + b0, acc[nt][1] + b1);
        if (grB < N)
            *(float2*)&out[(size_t)grB * 128 + c0] =
                make_float2(acc[nt][2] + b0, acc[nt][3] + b1);
    }
}

// ---------------------------------------------------------------------------

extern "C" void kernel_launch(void* const* d_in, const int* in_sizes, int n_in,
                              void* d_out, int out_size) {
    const float* x     = (const float*)d_in[0];
    const int*   ei    = (const int*)d_in[1];
    const float* Wg    = (const float*)d_in[2];
    const float* bg    = (const float*)d_in[3];
    const float* att_s = (const float*)d_in[4];
    const float* att_d = (const float*)d_in[5];
    const float* We    = (const float*)d_in[6];
    const float* be    = (const float*)d_in[7];
    const float* Wd    = (const float*)d_in[8];
    const float* bd    = (const float*)d_in[9];
    const float* Wo    = (const float*)d_in[10];
    const float* bo    = (const float*)d_in[11];
    float* out = (float*)d_out;

    int N = in_sizes[0] / 128;
    int E = in_sizes[1] / 2;

    cudaFuncSetAttribute(k1_gat, cudaFuncAttributeMaxDynamicSharedMemorySize, SMEM_TOT);
    cudaFuncSetAttribute(k_tail, cudaFuncAttributeMaxDynamicSharedMemorySize, SMEM_TOT);

    int nb = (N + TM - 1) / TM;

    k_prep<<<129, 128>>>(We, Wd, be, bd);
    k_prep2<<<128, 128>>>(Wg, Wo);
    k1_gat<<<nb, 256, SMEM_TOT>>>(x, att_s, att_d, N);
    k_edge<<<(E + 7) / 8, 256>>>(ei, E);
    k_tail<<<nb, 256, SMEM_TOT>>>(bg, bo, out, N);
}

// round 7
// speedup vs baseline: 1.7108x; 1.1534x over previous
#include <cuda_runtime.h>
#include <cuda_bf16.h>
#include <math.h>
#include <stdint.h>

// ---------------------------------------------------------------------------
// GAT (4x32 heads) + autoencoder head. R7: edge scatter -> CSR build + warp-
// per-node register gather (no atomics on the 512B agg rows). GEMMs as R6
// (mma.sync bf16 hi/lo split, 3 passes).
// ---------------------------------------------------------------------------

#define MAXN 50176                    // 196 * 256
#define MAXE 800000
#define TM 64
#define KS2 264
#define SM_B (TM * KS2 * 2)
#define SMEM_TOT (SM_B + 128 * KS2 * 2)

__device__ __align__(16) float g_h[MAXN * 128];
__device__ __align__(16) float g_agg[MAXN * 128];
__device__ __align__(16) float g_asrc[MAXN * 4];
__device__ __align__(16) float g_adst[MAXN * 4];
__device__ __align__(16) float g_denom[MAXN * 4];
__device__ __align__(16) float g_Wcd[128 * 128];
__device__ __align__(16) float g_bcd[128];
__device__ __align__(16) __nv_bfloat16 g_BgT[128 * KS2];
__device__ __align__(16) __nv_bfloat16 g_BcdT[128 * KS2];
__device__ __align__(16) __nv_bfloat16 g_BoT[128 * KS2];
// CSR scratch
__device__ int g_cnt[MAXN];
__device__ int g_start[MAXN + 1];
__device__ int g_blk[256];
__device__ int g_srcs[MAXE];

__device__ __forceinline__ float lrelu(float v) { return v > 0.f ? v : 0.2f * v; }
__device__ __forceinline__ float elu(float v)   { return v > 0.f ? v : (expf(v) - 1.f); }

__device__ __forceinline__ uint32_t smem_u32(const void* p) {
    uint32_t a;
    asm("{ .reg .u64 t; cvta.to.shared.u64 t, %1; cvt.u32.u64 %0, t; }" : "=r"(a) : "l"(p));
    return a;
}

#define LDSM_X4(r0, r1, r2, r3, addr)                                         \
    asm volatile("ldmatrix.sync.aligned.m8n8.x4.shared.b16 {%0,%1,%2,%3}, [%4];" \
                 : "=r"(r0), "=r"(r1), "=r"(r2), "=r"(r3) : "r"(addr))
#define MMA(c, a0, a1, a2, a3, b0, b1)                                        \
    asm volatile("mma.sync.aligned.m16n8k16.row.col.f32.bf16.bf16.f32 "       \
                 "{%0,%1,%2,%3}, {%4,%5,%6,%7}, {%8,%9}, {%0,%1,%2,%3};"      \
                 : "+f"((c)[0]), "+f"((c)[1]), "+f"((c)[2]), "+f"((c)[3])     \
                 : "r"(a0), "r"(a1), "r"(a2), "r"(a3), "r"(b0), "r"(b1))

__device__ __forceinline__ void split2(char* base, int r, int k, float a, float b) {
    __nv_bfloat16 ha = __float2bfloat16(a), hb = __float2bfloat16(b);
    __nv_bfloat162 hp; hp.x = ha; hp.y = hb;
    __nv_bfloat162 lp;
    lp.x = __float2bfloat16(a - __bfloat162float(ha));
    lp.y = __float2bfloat16(b - __bfloat162float(hb));
    *(__nv_bfloat162*)(base + (size_t)(r * KS2 + k) * 2)       = hp;
    *(__nv_bfloat162*)(base + (size_t)(r * KS2 + k + 128) * 2) = lp;
}

__device__ __forceinline__ void gemm3(uint32_t sbA, uint32_t sbB,
                                      int wm, int wn, int lane, float acc[8][4]) {
    uint32_t arow = (uint32_t)(wm * 16 + (lane & 15));
    uint32_t aka  = (uint32_t)((lane >> 4) * 8);
    uint32_t brow = (uint32_t)(wn * 64 + ((lane >> 4) << 3) + (lane & 7));
    uint32_t bka  = (uint32_t)(((lane >> 3) & 1) * 8);
    #pragma unroll
    for (int p = 0; p < 3; p++) {
        int aOff = (p == 1) ? 128 : 0;
        int bOff = (p == 2) ? 128 : 0;
        uint32_t abase = sbA + (arow * KS2 + aOff + aka) * 2;
        uint32_t bbase = sbB + (brow * KS2 + bOff + bka) * 2;
        #pragma unroll
        for (int kc = 0; kc < 8; kc++) {
            uint32_t a0, a1, a2, a3;
            LDSM_X4(a0, a1, a2, a3, abase + kc * 32);
            #pragma unroll
            for (int np = 0; np < 4; np++) {
                uint32_t b0, b1, b2, b3;
                LDSM_X4(b0, b1, b2, b3, bbase + np * (16 * KS2 * 2) + kc * 32);
                MMA(acc[2 * np],     a0, a1, a2, a3, b0, b1);
                MMA(acc[2 * np + 1], a0, a1, a2, a3, b2, b3);
            }
        }
    }
}

__device__ __forceinline__ void copyB(char* smem, const __nv_bfloat16* src, int tid) {
    const float4* s4 = (const float4*)src;
    float4* d4 = (float4*)(smem + SM_B);
    #pragma unroll 4
    for (int i = tid; i < 128 * KS2 / 8; i += 256) d4[i] = s4[i];
}

// ------------------------------- CSR build ---------------------------------
__global__ void k_zero() {
    int i = blockIdx.x * 256 + threadIdx.x;
    if (i < MAXN) g_cnt[i] = 0;
}
__global__ void k_hist(const int* __restrict__ ei, int E) {
    int e = blockIdx.x * 256 + threadIdx.x;
    if (e < E) atomicAdd(&g_cnt[ei[E + e]], 1);
}
__global__ void k_scanA() {                       // block sums
    __shared__ int s[256];
    int i = blockIdx.x * 256 + threadIdx.x;
    int v = g_cnt[i];
    s[threadIdx.x] = v;
    __syncthreads();
    for (int off = 128; off > 0; off >>= 1) {
        if (threadIdx.x < off) s[threadIdx.x] += s[threadIdx.x + off];
        __syncthreads();
    }
    if (threadIdx.x == 0) g_blk[blockIdx.x] = s[0];
}
__global__ void k_scanB(int nblk) {               // exclusive scan of block sums
    __shared__ int s[256];
    int t = threadIdx.x;
    s[t] = (t < nblk) ? g_blk[t] : 0;
    __syncthreads();
    for (int off = 1; off < 256; off <<= 1) {
        int v = (t >= off) ? s[t - off] : 0;
        __syncthreads();
        s[t] += v;
        __syncthreads();
    }
    if (t < nblk) g_blk[t] = s[t] - ((t < nblk) ? g_blk[t] : 0) + 0;  // inclusive - self = exclusive
}
__global__ void k_scanC() {                       // per-element exclusive start
    __shared__ int s[256];
    int i = blockIdx.x * 256 + threadIdx.x;
    int t = threadIdx.x;
    int c = g_cnt[i];
    s[t] = c;
    __syncthreads();
    for (int off = 1; off < 256; off <<= 1) {
        int v = (t >= off) ? s[t - off] : 0;
        __syncthreads();
        s[t] += v;
        __syncthreads();
    }
    g_start[i] = g_blk[blockIdx.x] + s[t] - c;    // exclusive
    g_cnt[i] = 0;                                 // reset as cursor
    if (i == MAXN - 1) g_start[MAXN] = g_blk[blockIdx.x] + s[t];
}
__global__ void k_fill(const int* __restrict__ ei, int E) {
    int e = blockIdx.x * 256 + threadIdx.x;
    if (e >= E) return;
    int d = ei[E + e];
    int pos = atomicAdd(&g_cnt[d], 1);
    g_srcs[g_start[d] + pos] = ei[e];
}

// ---------------------------------------------------------------------------
__global__ void k_prep(const float* __restrict__ We, const float* __restrict__ Wd,
                       const float* __restrict__ be, const float* __restrict__ bd) {
    int r = blockIdx.x, j = threadIdx.x;
    if (r < 128) {
        float a = 0.f;
        #pragma unroll
        for (int k = 0; k < 64; k++) a += We[r * 64 + k] * Wd[k * 128 + j];
        g_Wcd[r * 128 + j] = a;
    } else {
        float a = bd[j];
        #pragma unroll
        for (int k = 0; k < 64; k++) a += be[k] * Wd[k * 128 + j];
        g_bcd[j] = a;
    }
}

__global__ void k_prep2(const float* __restrict__ Wg, const float* __restrict__ Wo) {
    int n = blockIdx.x, k = threadIdx.x;
    float v;
    __nv_bfloat16 hb;
    v = Wg[k * 128 + n]; hb = __float2bfloat16(v);
    g_BgT[n * KS2 + k] = hb;
    g_BgT[n * KS2 + 128 + k] = __float2bfloat16(v - __bfloat162float(hb));
    v = g_Wcd[k * 128 + n]; hb = __float2bfloat16(v);
    g_BcdT[n * KS2 + k] = hb;
    g_BcdT[n * KS2 + 128 + k] = __float2bfloat16(v - __bfloat162float(hb));
    v = Wo[k * 128 + n]; hb = __float2bfloat16(v);
    g_BoT[n * KS2 + k] = hb;
    g_BoT[n * KS2 + 128 + k] = __float2bfloat16(v - __bfloat162float(hb));
}

// ---------------------------------------------------------------------------
// k1_gat: h = x @ W_gat (tensor); epilogue: logits + self-loop init.
// ---------------------------------------------------------------------------
__global__ __launch_bounds__(256, 2) void k1_gat(
    const float* __restrict__ x, const float* __restrict__ att_s,
    const float* __restrict__ att_d, int N) {
    extern __shared__ char smem[];
    uint32_t sb = smem_u32(smem);
    int tid = threadIdx.x, wid = tid >> 5, lane = tid & 31;
    int wm = wid >> 1, wn = wid & 1;
    int row0 = blockIdx.x * TM;

    const float4* x4 = (const float4*)x;
    for (int i = tid; i < TM * 32; i += 256) {
        int r = i >> 5, c4 = i & 31, gr = row0 + r;
        float4 v = (gr < N) ? x4[(size_t)gr * 32 + c4] : make_float4(0.f, 0.f, 0.f, 0.f);
        split2(smem, r, c4 * 4, v.x, v.y);
        split2(smem, r, c4 * 4 + 2, v.z, v.w);
    }
    copyB(smem, g_BgT, tid);
    __syncthreads();

    float acc[8][4];
    #pragma unroll
    for (int i = 0; i < 8; i++)
        #pragma unroll
        for (int j = 0; j < 4; j++) acc[i][j] = 0.f;
    gemm3(sb, sb + SM_B, wm, wn, lane, acc);

    int g = lane >> 2, q = lane & 3;
    int grA = row0 + wm * 16 + g;
    int grB = grA + 8;
    float pa[2], pb[2];
    #pragma unroll
    for (int hl = 0; hl < 2; hl++) {
        int hh = wn * 2 + hl;
        float sAs = 0.f, sAd = 0.f, sBs = 0.f, sBd = 0.f;
        #pragma unroll
        for (int t = 0; t < 4; t++) {
            int nt = hl * 4 + t;
            int c0 = wn * 64 + nt * 8 + q * 2;
            float w0s = __ldg(&att_s[c0]), w1s = __ldg(&att_s[c0 + 1]);
            float w0d = __ldg(&att_d[c0]), w1d = __ldg(&att_d[c0 + 1]);
            sAs += acc[nt][0] * w0s + acc[nt][1] * w1s;
            sAd += acc[nt][0] * w0d + acc[nt][1] * w1d;
            sBs += acc[nt][2] * w0s + acc[nt][3] * w1s;
            sBd += acc[nt][2] * w0d + acc[nt][3] * w1d;
        }
        #pragma unroll
        for (int off = 1; off <= 2; off <<= 1) {
            sAs += __shfl_xor_sync(0xffffffffu, sAs, off);
            sAd += __shfl_xor_sync(0xffffffffu, sAd, off);
            sBs += __shfl_xor_sync(0xffffffffu, sBs, off);
            sBd += __shfl_xor_sync(0xffffffffu, sBd, off);
        }
        pa[hl] = expf(lrelu(sAs + sAd));
        pb[hl] = expf(lrelu(sBs + sBd));
        if (q == 0) {
            if (grA < N) {
                g_asrc[grA * 4 + hh] = sAs; g_adst[grA * 4 + hh] = sAd;
                g_denom[grA * 4 + hh] = pa[hl];
            }
            if (grB < N) {
                g_asrc[grB * 4 + hh] = sBs; g_adst[grB * 4 + hh] = sBd;
                g_denom[grB * 4 + hh] = pb[hl];
            }
        }
    }
    #pragma unroll
    for (int nt = 0; nt < 8; nt++) {
        int c0 = wn * 64 + nt * 8 + q * 2;
        float pA = pa[nt >> 2], pB = pb[nt >> 2];
        if (grA < N) {
            *(float2*)&g_h[(size_t)grA * 128 + c0] = make_float2(acc[nt][0], acc[nt][1]);
            *(float2*)&g_agg[(size_t)grA * 128 + c0] =
                make_float2(pA * acc[nt][0], pA * acc[nt][1]);
        }
        if (grB < N) {
            *(float2*)&g_h[(size_t)grB * 128 + c0] = make_float2(acc[nt][2], acc[nt][3]);
            *(float2*)&g_agg[(size_t)grB * 128 + c0] =
                make_float2(pB * acc[nt][2], pB * acc[nt][3]);
        }
    }
}

// ---------------------------------------------------------------------------
// k_gather: one warp per dst node. Register accumulation over CSR edge list
// (2-way software pipeline), then single write of agg/denom. No atomics.
// ---------------------------------------------------------------------------
__global__ __launch_bounds__(256) void k_gather(int N) {
    int d = blockIdx.x * 8 + (threadIdx.x >> 5);
    if (d >= N) return;
    int lane = threadIdx.x & 31;

    float4 ad = ((const float4*)g_adst)[d];
    float adv = lane < 16 ? (lane < 8 ? ad.x : ad.y) : (lane < 24 ? ad.z : ad.w);

    // self-loop init from k1_gat
    float4 acc = ((const float4*)g_agg)[(size_t)d * 32 + lane];
    float den = 0.f;

    int beg = g_start[d], end = g_start[d + 1];
    int i = beg;
    for (; i + 1 < end; i += 2) {
        int s0 = g_srcs[i], s1 = g_srcs[i + 1];
        float4 as0 = ((const float4*)g_asrc)[s0];
        float4 as1 = ((const float4*)g_asrc)[s1];
        float4 h0 = ((const float4*)g_h)[(size_t)s0 * 32 + lane];
        float4 h1 = ((const float4*)g_h)[(size_t)s1 * 32 + lane];
        float a0 = lane < 16 ? (lane < 8 ? as0.x : as0.y) : (lane < 24 ? as0.z : as0.w);
        float a1 = lane < 16 ? (lane < 8 ? as1.x : as1.y) : (lane < 24 ? as1.z : as1.w);
        float e0 = a0 + adv, e1 = a1 + adv;
        float p0 = expf(e0 > 0.f ? e0 : 0.2f * e0);
        float p1 = expf(e1 > 0.f ? e1 : 0.2f * e1);
        den += p0 + p1;
        acc.x = fmaf(p0, h0.x, fmaf(p1, h1.x, acc.x));
        acc.y = fmaf(p0, h0.y, fmaf(p1, h1.y, acc.y));
        acc.z = fmaf(p0, h0.z, fmaf(p1, h1.z, acc.z));
        acc.w = fmaf(p0, h0.w, fmaf(p1, h1.w, acc.w));
    }
    if (i < end) {
        int s0 = g_srcs[i];
        float4 as0 = ((const float4*)g_asrc)[s0];
        float4 h0 = ((const float4*)g_h)[(size_t)s0 * 32 + lane];
        float a0 = lane < 16 ? (lane < 8 ? as0.x : as0.y) : (lane < 24 ? as0.z : as0.w);
        float e0 = a0 + adv;
        float p0 = expf(e0 > 0.f ? e0 : 0.2f * e0);
        den += p0;
        acc.x = fmaf(p0, h0.x, acc.x);
        acc.y = fmaf(p0, h0.y, acc.y);
        acc.z = fmaf(p0, h0.z, acc.z);
        acc.w = fmaf(p0, h0.w, acc.w);
    }

    ((float4*)g_agg)[(size_t)d * 32 + lane] = acc;
    if ((lane & 7) == 0)
        g_denom[d * 4 + (lane >> 3)] += den;      // add edge sum to self term
}

// ---------------------------------------------------------------------------
// k_tail (unchanged from R6)
// ---------------------------------------------------------------------------
__global__ __launch_bounds__(256, 2) void k_tail(
    const float* __restrict__ bg, const float* __restrict__ bo,
    float* __restrict__ out, int N) {
    extern __shared__ char smem[];
    uint32_t sb = smem_u32(smem);
    int tid = threadIdx.x, wid = tid >> 5, lane = tid & 31;
    int wm = wid >> 1, wn = wid & 1;
    int row0 = blockIdx.x * TM;

    const float4* agg4 = (const float4*)g_agg;
    const float4* bg4 = (const float4*)bg;
    for (int i = tid; i < TM * 32; i += 256) {
        int r = i >> 5, c4 = i & 31, gr = row0 + r;
        float4 v = make_float4(0.f, 0.f, 0.f, 0.f);
        if (gr < N) {
            float4 a = agg4[(size_t)gr * 32 + c4];
            float inv = 1.f / (g_denom[gr * 4 + (c4 >> 3)] + 1e-16f);
            float4 b = bg4[c4];
            v.x = elu(a.x * inv + b.x); v.y = elu(a.y * inv + b.y);
            v.z = elu(a.z * inv + b.z); v.w = elu(a.w * inv + b.w);
        }
        split2(smem, r, c4 * 4, v.x, v.y);
        split2(smem, r, c4 * 4 + 2, v.z, v.w);
    }
    copyB(smem, g_BcdT, tid);
    __syncthreads();

    float acc[8][4];
    #pragma unroll
    for (int i = 0; i < 8; i++)
        #pragma unroll
        for (int j = 0; j < 4; j++) acc[i][j] = 0.f;
    gemm3(sb, sb + SM_B, wm, wn, lane, acc);
    __syncthreads();

    int g = lane >> 2, q = lane & 3;
    int lrA = wm * 16 + g, lrB = lrA + 8;
    #pragma unroll
    for (int nt = 0; nt < 8; nt++) {
        int c0 = wn * 64 + nt * 8 + q * 2;
        float bc0 = g_bcd[c0], bc1 = g_bcd[c0 + 1];
        split2(smem, lrA, c0, elu(acc[nt][0] + bc0), elu(acc[nt][1] + bc1));
        split2(smem, lrB, c0, elu(acc[nt][2] + bc0), elu(acc[nt][3] + bc1));
    }
    copyB(smem, g_BoT, tid);
    __syncthreads();

    #pragma unroll
    for (int i = 0; i < 8; i++)
        #pragma unroll
        for (int j = 0; j < 4; j++) acc[i][j] = 0.f;
    gemm3(sb, sb + SM_B, wm, wn, lane, acc);

    int grA = row0 + lrA, grB = row0 + lrB;
    #pragma unroll
    for (int nt = 0; nt < 8; nt++) {
        int c0 = wn * 64 + nt * 8 + q * 2;
        float b0 = __ldg(&bo[c0]), b1 = __ldg(&bo[c0 + 1]);
        if (grA < N)
            *(float2*)&out[(size_t)grA * 128 + c0] =
                make_float2(acc[nt][0] + b0, acc[nt][1] + b1);
        if (grB < N)
            *(float2*)&out[(size_t)grB * 128 + c0] =
                make_float2(acc[nt][2] + b0, acc[nt][3] + b1);
    }
}

// ---------------------------------------------------------------------------

extern "C" void kernel_launch(void* const* d_in, const int* in_sizes, int n_in,
                              void* d_out, int out_size) {
    const float* x     = (const float*)d_in[0];
    const int*   ei    = (const int*)d_in[1];
    const float* Wg    = (const float*)d_in[2];
    const float* bg    = (const float*)d_in[3];
    const float* att_s = (const float*)d_in[4];
    const float* att_d = (const float*)d_in[5];
    const float* We    = (const float*)d_in[6];
    const float* be    = (const float*)d_in[7];
    const float* Wd    = (const float*)d_in[8];
    const float* bd    = (const float*)d_in[9];
    const float* Wo    = (const float*)d_in[10];
    const float* bo    = (const float*)d_in[11];
    float* out = (float*)d_out;

    int N = in_sizes[0] / 128;
    int E = in_sizes[1] / 2;

    cudaFuncSetAttribute(k1_gat, cudaFuncAttributeMaxDynamicSharedMemorySize, SMEM_TOT);
    cudaFuncSetAttribute(k_tail, cudaFuncAttributeMaxDynamicSharedMemorySize, SMEM_TOT);

    int nb = (N + TM - 1) / TM;
    int eb = (E + 255) / 256;

    // CSR build (depends only on edge_index)
    k_zero<<<MAXN / 256, 256>>>();
    k_hist<<<eb, 256>>>(ei, E);
    k_scanA<<<MAXN / 256, 256>>>();
    k_scanB<<<1, 256>>>(MAXN / 256);
    k_scanC<<<MAXN / 256, 256>>>();
    k_fill<<<eb, 256>>>(ei, E);
    // dense pipeline
    k_prep<<<129, 128>>>(We, Wd, be, bd);
    k_prep2<<<128, 128>>>(Wg, Wo);
    k1_gat<<<nb, 256, SMEM_TOT>>>(x, att_s, att_d, N);
    k_gather<<<(N + 7) / 8, 256>>>(N);
    k_tail<<<nb, 256, SMEM_TOT>>>(bg, bo, out, N);
}